// round 1
// baseline (speedup 1.0000x reference)
#include <cuda_runtime.h>
#include <math.h>

#define B_  1024
#define N_  1024
#define M_  128
#define C_  1024
#define OUTF 390
#define EPS 1e-16f

// ---------------- scratch ----------------
__device__ float g_o[B_ * OUTF];        // GEMM output (k|beta|g|s0..2|gamma|e|a), e sigmoided in place
__device__ float g_logits[B_ * N_];     // beta * cosine sim
__device__ float g_scal[B_ * 8];        // [0]=beta [1]=g [2]=gamma [3]=knorm [4..6]=s0..s2

// ---------------- K1: SGEMM 1024 x 390 x 1024 ----------------
// 64x64 block tile, 16x16 threads, 4x4 micro tile, BK=16
__global__ void k1_gemm(const float* __restrict__ A,   // emb (B_ x C_)
                        const float* __restrict__ Bm,  // fc_w (C_ x OUTF)
                        const float* __restrict__ bias)
{
    __shared__ float As[16][65];   // [kk][row]
    __shared__ float Bs[16][68];   // [kk][col]

    const int tid = threadIdx.x;           // 0..255
    const int tx  = tid & 15;              // col group
    const int ty  = tid >> 4;              // row group
    const int row0 = blockIdx.y * 64;
    const int col0 = blockIdx.x * 64;

    float acc[4][4];
#pragma unroll
    for (int i = 0; i < 4; i++)
#pragma unroll
        for (int j = 0; j < 4; j++) acc[i][j] = 0.f;

    // A-tile load mapping: thread t loads one float4
    const int ar  = tid >> 2;        // 0..63 row within tile
    const int ac4 = (tid & 3) * 4;   // k offset 0,4,8,12
    // B-tile load mapping: thread t loads 4 scalars
    const int bkr = tid >> 4;        // 0..15 k row
    const int bcc = (tid & 15) * 4;  // col offset

    for (int k0 = 0; k0 < C_; k0 += 16) {
        float4 av = *(const float4*)&A[(size_t)(row0 + ar) * C_ + k0 + ac4];
        As[ac4 + 0][ar] = av.x;
        As[ac4 + 1][ar] = av.y;
        As[ac4 + 2][ar] = av.z;
        As[ac4 + 3][ar] = av.w;
#pragma unroll
        for (int j = 0; j < 4; j++) {
            int col = col0 + bcc + j;
            Bs[bkr][bcc + j] = (col < OUTF) ? Bm[(size_t)(k0 + bkr) * OUTF + col] : 0.f;
        }
        __syncthreads();

#pragma unroll
        for (int kk = 0; kk < 16; kk++) {
            float ra[4], rb[4];
#pragma unroll
            for (int i = 0; i < 4; i++) ra[i] = As[kk][ty * 4 + i];
            float4 rb4 = *(const float4*)&Bs[kk][tx * 4];
            rb[0] = rb4.x; rb[1] = rb4.y; rb[2] = rb4.z; rb[3] = rb4.w;
#pragma unroll
            for (int i = 0; i < 4; i++)
#pragma unroll
                for (int j = 0; j < 4; j++) acc[i][j] = fmaf(ra[i], rb[j], acc[i][j]);
        }
        __syncthreads();
    }

#pragma unroll
    for (int i = 0; i < 4; i++) {
        int row = row0 + ty * 4 + i;
#pragma unroll
        for (int j = 0; j < 4; j++) {
            int col = col0 + tx * 4 + j;
            if (col < OUTF)
                g_o[(size_t)row * OUTF + col] = acc[i][j] + bias[col];
        }
    }
}

// ---------------- K2: per-batch activations + k-norm ----------------
__device__ __forceinline__ float softplus_f(float x) {
    return (x > 0.f) ? (x + log1pf(expf(-x))) : log1pf(expf(x));
}
__device__ __forceinline__ float sigmoid_f(float x) {
    return 1.f / (1.f + expf(-x));
}

__global__ void k2_act()   // grid = B_, block = 128
{
    const int b   = blockIdx.x;
    const int tid = threadIdx.x;
    float* o = &g_o[(size_t)b * OUTF];

    float kv = o[tid];
    float ss = kv * kv;
#pragma unroll
    for (int off = 16; off > 0; off >>= 1)
        ss += __shfl_xor_sync(0xffffffffu, ss, off);
    __shared__ float red[4];
    if ((tid & 31) == 0) red[tid >> 5] = ss;
    __syncthreads();

    if (tid == 0) {
        float ksq = red[0] + red[1] + red[2] + red[3];
        float knorm = sqrtf(ksq);
        float beta  = softplus_f(o[M_]);
        float g     = sigmoid_f(o[M_ + 1]);
        float s0 = o[M_ + 2], s1 = o[M_ + 3], s2 = o[M_ + 4];
        float mx = fmaxf(s0, fmaxf(s1, s2));
        float e0 = expf(s0 - mx), e1 = expf(s1 - mx), e2 = expf(s2 - mx);
        float es = e0 + e1 + e2;
        float gamma = 1.f + softplus_f(o[M_ + 5]);
        float* sc = &g_scal[b * 8];
        sc[0] = beta; sc[1] = g; sc[2] = gamma; sc[3] = knorm;
        sc[4] = e0 / es; sc[5] = e1 / es; sc[6] = e2 / es;
    }
    // sigmoid(e) in place
    o[M_ + 6 + tid] = sigmoid_f(o[M_ + 6 + tid]);
}

// ---------------- K3: logits = beta * cosine(memory_row, k) ----------------
// grid: (N_/32, B_), block 256 (8 warps), each warp handles 4 rows
__global__ void k3_sim(const float* __restrict__ mem)
{
    const int b    = blockIdx.y;
    const int tid  = threadIdx.x;
    const int warp = tid >> 5;
    const int lane = tid & 31;

    __shared__ float sk[M_];
    if (tid < M_) sk[tid] = g_o[(size_t)b * OUTF + tid];
    __syncthreads();

    const float beta  = g_scal[b * 8 + 0];
    const float knorm = g_scal[b * 8 + 3];
    const float4 k4   = *(const float4*)&sk[lane * 4];

    const int nbase = blockIdx.x * 32 + warp * 4;
    float dot[4], ssq[4];
#pragma unroll
    for (int i = 0; i < 4; i++) {
        const float4 mv = *(const float4*)&mem[((size_t)b * N_ + (nbase + i)) * M_ + lane * 4];
        dot[i] = mv.x * k4.x + mv.y * k4.y + mv.z * k4.z + mv.w * k4.w;
        ssq[i] = mv.x * mv.x + mv.y * mv.y + mv.z * mv.z + mv.w * mv.w;
    }
#pragma unroll
    for (int off = 16; off > 0; off >>= 1) {
#pragma unroll
        for (int i = 0; i < 4; i++) {
            dot[i] += __shfl_xor_sync(0xffffffffu, dot[i], off);
            ssq[i] += __shfl_xor_sync(0xffffffffu, ssq[i], off);
        }
    }
    if (lane < 4) {
        int i = lane;
        float sim = dot[i] / (sqrtf(ssq[i]) * knorm + EPS);
        g_logits[(size_t)b * N_ + nbase + i] = beta * sim;
    }
}

// ---------------- K4: softmax -> gate -> shift conv -> sharpen -> w ----------------
// grid = B_, block = 256, each thread handles 4 elements (i = tid + 256*j)
__global__ void k4_weight(const float* __restrict__ w_prev, float* __restrict__ w_out)
{
    const int b   = blockIdx.x;
    const int tid = threadIdx.x;

    __shared__ float swg[N_];
    __shared__ float sred[8];

    const float* lg = &g_logits[(size_t)b * N_];
    const float* sc = &g_scal[b * 8];
    const float g = sc[1], gamma = sc[2], s0 = sc[4], s1 = sc[5], s2 = sc[6];

    float x[4];
    float lmax = -1e30f;
#pragma unroll
    for (int j = 0; j < 4; j++) {
        x[j] = lg[tid + 256 * j];
        lmax = fmaxf(lmax, x[j]);
    }
#pragma unroll
    for (int off = 16; off > 0; off >>= 1)
        lmax = fmaxf(lmax, __shfl_xor_sync(0xffffffffu, lmax, off));
    if ((tid & 31) == 0) sred[tid >> 5] = lmax;
    __syncthreads();
    float bmax = sred[0];
#pragma unroll
    for (int k = 1; k < 8; k++) bmax = fmaxf(bmax, sred[k]);

    float p[4];
    float lsum = 0.f;
#pragma unroll
    for (int j = 0; j < 4; j++) { p[j] = expf(x[j] - bmax); lsum += p[j]; }
#pragma unroll
    for (int off = 16; off > 0; off >>= 1)
        lsum += __shfl_xor_sync(0xffffffffu, lsum, off);
    __syncthreads();             // protect sred reuse
    if ((tid & 31) == 0) sred[tid >> 5] = lsum;
    __syncthreads();
    float bsum = 0.f;
#pragma unroll
    for (int k = 0; k < 8; k++) bsum += sred[k];
    float inv = 1.f / bsum;

    const float* wp = &w_prev[(size_t)b * N_];
#pragma unroll
    for (int j = 0; j < 4; j++) {
        int i = tid + 256 * j;
        float wc = p[j] * inv;
        swg[i] = g * wc + (1.f - g) * wp[i];
    }
    __syncthreads();

    float wpow[4];
    float lsum2 = 0.f;
#pragma unroll
    for (int j = 0; j < 4; j++) {
        int i = tid + 256 * j;
        float wt = s0 * swg[(i + N_ - 1) & (N_ - 1)] + s1 * swg[i] + s2 * swg[(i + 1) & (N_ - 1)];
        wpow[j] = powf(wt + EPS, gamma);
        lsum2 += wpow[j];
    }
#pragma unroll
    for (int off = 16; off > 0; off >>= 1)
        lsum2 += __shfl_xor_sync(0xffffffffu, lsum2, off);
    __syncthreads();
    if ((tid & 31) == 0) sred[tid >> 5] = lsum2;
    __syncthreads();
    float bsum2 = 0.f;
#pragma unroll
    for (int k = 0; k < 8; k++) bsum2 += sred[k];
    float inv2 = 1.f / (bsum2 + EPS);

#pragma unroll
    for (int j = 0; j < 4; j++)
        w_out[(size_t)b * N_ + tid + 256 * j] = wpow[j] * inv2;
}

// ---------------- K5: new_memory = mem*(1 - w e) + w a ----------------
// grid: (N_/32, B_), block 256 (8 warps), each warp handles 4 rows
__global__ void k5_update(const float* __restrict__ mem,
                          const float* __restrict__ w,
                          float* __restrict__ out_mem)
{
    const int b    = blockIdx.y;
    const int tid  = threadIdx.x;
    const int warp = tid >> 5;
    const int lane = tid & 31;

    __shared__ float se[M_];
    __shared__ float sa[M_];
    if (tid < M_) {
        se[tid] = g_o[(size_t)b * OUTF + M_ + 6 + tid];       // sigmoid(e)
        sa[tid] = g_o[(size_t)b * OUTF + 2 * M_ + 6 + tid];   // a
    }
    __syncthreads();

    const float4 ev = *(const float4*)&se[lane * 4];
    const float4 av = *(const float4*)&sa[lane * 4];

    const int nbase = blockIdx.x * 32 + warp * 4;
#pragma unroll
    for (int i = 0; i < 4; i++) {
        const int n = nbase + i;
        const float wv = w[(size_t)b * N_ + n];
        const size_t off = ((size_t)b * N_ + n) * M_ + lane * 4;
        float4 mv = *(const float4*)&mem[off];
        float4 r;
        r.x = mv.x * (1.f - wv * ev.x) + wv * av.x;
        r.y = mv.y * (1.f - wv * ev.y) + wv * av.y;
        r.z = mv.z * (1.f - wv * ev.z) + wv * av.z;
        r.w = mv.w * (1.f - wv * ev.w) + wv * av.w;
        *(float4*)&out_mem[off] = r;
    }
}

// ---------------- launch ----------------
extern "C" void kernel_launch(void* const* d_in, const int* in_sizes, int n_in,
                              void* d_out, int out_size)
{
    const float* emb    = (const float*)d_in[0];   // B x C
    const float* w_prev = (const float*)d_in[1];   // B x N
    const float* mem    = (const float*)d_in[2];   // B x N x M
    const float* fc_w   = (const float*)d_in[3];   // C x OUTF
    const float* fc_b   = (const float*)d_in[4];   // OUTF

    float* out_w   = (float*)d_out;                // B x N
    float* out_mem = out_w + (size_t)B_ * N_;      // B x N x M

    dim3 g1((OUTF + 63) / 64, B_ / 64);
    k1_gemm<<<g1, 256>>>(emb, fc_w, fc_b);

    k2_act<<<B_, 128>>>();

    dim3 g3(N_ / 32, B_);
    k3_sim<<<g3, 256>>>(mem);

    k4_weight<<<B_, 256>>>(w_prev, out_w);

    k5_update<<<g3, 256>>>(mem, out_w, out_mem);
}